// round 16
// baseline (speedup 1.0000x reference)
#include <cuda_runtime.h>
#include <cuda_bf16.h>
#include <cstdint>
#include <math.h>

// Problem constants
#define T_TOK 8192
#define HDIM  1024
#define NEXP  8
#define CAP   4096

// GEMM tiling: CTA 128x128, 4 warps of 64x64.
// B: warp-private 3-stage cp.async SMEM pipeline, tile-major gmem source.
// A: direct LDG.128 fragments with 1-chunk register prefetch.
#define TM 128
#define TN 128
#define NCH 32
#define BSTG 4096
#define NST 3
#define SMEM_BYTES (4 * NST * BSTG)   // 48KB per CTA

// ---------------- scratch (device globals, zero-init at load) ---------------
// xb:  token-row-major (gather needs it):   [tok][c][slot]   row = 2048B
// w*b: tile-major: [e][c][n][slot]          offset=((e*32+c)*1024+n)*64
// h1b: tile-major: [e][c][r][slot]          offset=((e*32+c)*CAP +r)*64
__device__ int   g_cnt[NEXP];
__device__ int   g_tok[NEXP * CAP];
__device__ float g_wgt[NEXP * CAP];
__device__ uint4 g_xb [(size_t)T_TOK * 128];        // 16MB
__device__ uint4 g_w1b[(size_t)NEXP * HDIM * 128];  // 16MB
__device__ uint4 g_w2b[(size_t)NEXP * HDIM * 128];  // 16MB
__device__ uint4 g_h1b[(size_t)NEXP * CAP * 128];   // 64MB

// ---------------- helpers ----------------------------------------------------
__device__ __forceinline__ uint32_t smem_u32(const void* p) {
    uint32_t a;
    asm("{ .reg .u64 t; cvta.to.shared.u64 t, %1; cvt.u32.u64 %0, t; }" : "=r"(a) : "l"(p));
    return a;
}
__device__ __forceinline__ uint32_t pack2(float lo, float hi) {
    uint32_t r;
    asm("cvt.rn.bf16x2.f32 %0, %1, %2;" : "=r"(r) : "f"(hi), "f"(lo));
    return r;
}
__device__ __forceinline__ uint4 lds128(uint32_t addr) {
    uint4 v;
    asm volatile("ld.shared.v4.b32 {%0,%1,%2,%3}, [%4];"
                 : "=r"(v.x), "=r"(v.y), "=r"(v.z), "=r"(v.w) : "r"(addr));
    return v;
}
__device__ __forceinline__ void cp16ca(uint32_t dst, const void* src) {
    asm volatile("cp.async.ca.shared.global [%0], [%1], 16;" :: "r"(dst), "l"(src));
}
#define CP_COMMIT() asm volatile("cp.async.commit_group;" ::: "memory")
#define CP_WAIT1()  asm volatile("cp.async.wait_group 1;" ::: "memory")

__device__ __forceinline__ void mma16(float* c,
    uint32_t a0, uint32_t a1, uint32_t a2, uint32_t a3, uint32_t b0, uint32_t b1)
{
    asm volatile(
        "mma.sync.aligned.m16n8k16.row.col.f32.bf16.bf16.f32 "
        "{%0,%1,%2,%3}, {%4,%5,%6,%7}, {%8,%9}, {%0,%1,%2,%3};"
        : "+f"(c[0]), "+f"(c[1]), "+f"(c[2]), "+f"(c[3])
        : "r"(a0), "r"(a1), "r"(a2), "r"(a3), "r"(b0), "r"(b1));
}

// permute one 32-float chunk of `src` row into the bf16 slot layout
__device__ __forceinline__ void permute_chunk(
    const float* __restrict__ src, int row, int c, uint4* drow)
{
    const float4* s4 = (const float4*)(src + (size_t)row * HDIM + c * 32);
    float f[32];
#pragma unroll
    for (int i = 0; i < 8; i++) {
        float4 v = s4[i];
        f[4*i] = v.x; f[4*i+1] = v.y; f[4*i+2] = v.z; f[4*i+3] = v.w;
    }
    uint32_t p[16];
#pragma unroll
    for (int P = 0; P < 16; P++) p[P] = pack2(f[2*P], f[2*P+1]);
#pragma unroll
    for (int s = 0; s < 4; s++)
        drow[s] = make_uint4(p[s], p[s+4], p[s+8], p[s+12]);
}

// ---------------- fused setup: router / xb / w1b / residual copy -------------
__global__ __launch_bounds__(256) void setup_kernel(
    const float* __restrict__ x, const float* __restrict__ rw,
    const float* __restrict__ w1,
    float* __restrict__ out, int write_probs)
{
    if (blockIdx.y == 0) {
        // ---- router ----
        int t = blockIdx.x * 8 + (threadIdx.x >> 5);
        int lane = threadIdx.x & 31;

        float acc[NEXP];
#pragma unroll
        for (int e = 0; e < NEXP; e++) acc[e] = 0.f;
        const float* xp = x + (size_t)t * HDIM;
        for (int i = lane; i < HDIM; i += 32) {
            float xv = xp[i];
#pragma unroll
            for (int e = 0; e < NEXP; e++)
                acc[e] = fmaf(xv, rw[e * HDIM + i], acc[e]);
        }
#pragma unroll
        for (int e = 0; e < NEXP; e++)
#pragma unroll
            for (int off = 16; off; off >>= 1)
                acc[e] += __shfl_xor_sync(0xffffffffu, acc[e], off);

        if (lane == 0) {
            float m = acc[0];
#pragma unroll
            for (int e = 1; e < NEXP; e++) m = fmaxf(m, acc[e]);
            float p[NEXP]; float s = 0.f;
#pragma unroll
            for (int e = 0; e < NEXP; e++) { p[e] = expf(acc[e] - m); s += p[e]; }
            float inv_s = 1.f / s;
#pragma unroll
            for (int e = 0; e < NEXP; e++) p[e] *= inv_s;

            if (write_probs) {
                float* pr = out + (size_t)T_TOK * HDIM + (size_t)t * NEXP;
#pragma unroll
                for (int e = 0; e < NEXP; e++) pr[e] = p[e];
            }
            int i0 = 0;
#pragma unroll
            for (int e = 1; e < NEXP; e++) if (p[e] > p[i0]) i0 = e;
            int i1 = (i0 == 0) ? 1 : 0;
#pragma unroll
            for (int e = 0; e < NEXP; e++) if (e != i0 && p[e] > p[i1]) i1 = e;

            float v0 = p[i0], v1 = p[i1];
            float invw = 1.f / (v0 + v1);
            int pos0 = atomicAdd(&g_cnt[i0], 1);
            if (pos0 < CAP) { g_tok[i0 * CAP + pos0] = t; g_wgt[i0 * CAP + pos0] = v0 * invw; }
            int pos1 = atomicAdd(&g_cnt[i1], 1);
            if (pos1 < CAP) { g_tok[i1 * CAP + pos1] = t; g_wgt[i1 * CAP + pos1] = v1 * invw; }
        }
    } else if (blockIdx.y == 1) {
        // ---- xb: token-row-major permute ----
        int idx = blockIdx.x * 256 + threadIdx.x;
        int row = idx >> 5, c = idx & 31;
        permute_chunk(x, row, c, g_xb + ((size_t)row * 32 + c) * 4);
    } else if (blockIdx.y == 2) {
        // ---- w1b: tile-major permute ----
        int idx = blockIdx.x * 256 + threadIdx.x;
        int row = idx >> 5, c = idx & 31;
        int e = row >> 10, n = row & 1023;
        permute_chunk(w1, row, c, g_w1b + (((size_t)(e * 32 + c)) * HDIM + n) * 4);
    } else {
        // ---- residual copy: out[0:T*H] = x ----
        const float4* s = (const float4*)x;
        float4* d = (float4*)out;
        int t0 = blockIdx.x * 256 + threadIdx.x;
#pragma unroll
        for (int i = 0; i < 8; i++)
            d[t0 + i * 262144] = s[t0 + i * 262144];
    }
}

// ---------------- compute: B fragments from warp-private SMEM, A from regs ---
__device__ __forceinline__ void compute_chunkB(
    uint32_t breg, const uint4 a[8], float acc[4][8][4], int gid, int tig)
{
    uint32_t toff = (uint32_t)((tig ^ ((gid >> 1) & 3)) * 16);
#pragma unroll
    for (int ni = 0; ni < 8; ni++) {
        uint4 fb = lds128(breg + (ni * 8 + gid) * 64 + toff);
#pragma unroll
        for (int mi = 0; mi < 4; mi++) {
            float* c = acc[mi][ni];
            mma16(c, a[mi*2].x, a[mi*2+1].x, a[mi*2].y, a[mi*2+1].y, fb.x, fb.y);
            mma16(c, a[mi*2].z, a[mi*2+1].z, a[mi*2].w, a[mi*2+1].w, fb.z, fb.w);
        }
    }
}

// stage B chunk cc (tile-major source: 512B contiguous per cp.async instr)
#define STAGE_B(cc, st) do { \
    uint32_t _d = wbase + (uint32_t)(st) * BSTG + dstoff; \
    uint32_t _g = (uint32_t)(cc) * 65536; \
    _Pragma("unroll") \
    for (int i = 0; i < 8; i++) \
        cp16ca(_d + i * 512, bbase + _g + i * 512); \
} while (0)

#define LOAD_A(dst, cc, astride) do { \
    _Pragma("unroll") \
    for (int i = 0; i < 8; i++) \
        (dst)[i] = __ldg((const uint4*)(abase + aoff[i] + (uint32_t)(cc) * (astride))); \
} while (0)

#define MAINLOOP(astride) do { \
    LOAD_A(a0, 0, astride); \
    STAGE_B(0, 0); CP_COMMIT(); \
    STAGE_B(1, 1); CP_COMMIT(); \
    int fill = 2, cur = 0; \
    for (int c = 0; c < NCH; c += 2) { \
        CP_WAIT1(); __syncwarp(); \
        if (c + 2 < NCH) STAGE_B(c + 2, fill); \
        CP_COMMIT(); \
        fill = (fill == 2) ? 0 : fill + 1; \
        LOAD_A(a1, c + 1, astride); \
        compute_chunkB(wbase + cur * BSTG, a0, acc, gid, tig); \
        cur = (cur == 2) ? 0 : cur + 1; \
        CP_WAIT1(); __syncwarp(); \
        if (c + 3 < NCH) STAGE_B(c + 3, fill); \
        CP_COMMIT(); \
        fill = (fill == 2) ? 0 : fill + 1; \
        if (c + 2 < NCH) LOAD_A(a0, c + 2, astride); \
        compute_chunkB(wbase + cur * BSTG, a1, acc, gid, tig); \
        cur = (cur == 2) ? 0 : cur + 1; \
    } \
} while (0)

// ---------------- GEMM1: h1b = relu(xb[gather] @ W1b^T + b1) -----------------
// grid.x in [0,8): compute tiles; grid.x in [8,16): W2 bf16 tile-major convert
// (w2b is consumed only by gemm2, which launches after gemm1 completes).
__global__ __launch_bounds__(128, 2) void gemm1_tc(
    const float* __restrict__ b1, const float* __restrict__ w2)
{
    extern __shared__ char smem[];
    if (blockIdx.x >= 8) {
        int idx = (blockIdx.x - 8) + 8 * (blockIdx.y + 32 * blockIdx.z);
        int task = threadIdx.x + idx * 128;
        int row = task >> 5, c = task & 31;
        int e = row >> 10, n = row & 1023;
        permute_chunk(w2, row, c, g_w2b + (((size_t)(e * 32 + c)) * HDIM + n) * 4);
        return;
    }

    int e = blockIdx.z;
    int count = min(g_cnt[e], CAP);
    int m0 = blockIdx.y * TM;
    if (m0 >= count) return;
    int n0 = blockIdx.x * TN;

    uint32_t sb = smem_u32(smem);
    int tid = threadIdx.x, wid = tid >> 5, lane = tid & 31;
    int wm = wid >> 1, wn = wid & 1, gid = lane >> 2, tig = lane & 3;

    // B staging: tile-major w1b; per-lane contiguous source offset
    int sl = lane & 3, lr = lane >> 2;
    int sig = (lr >> 1) & 3;
    uint32_t dstoff = (uint32_t)(lr * 64 + ((sl ^ sig) * 16));
    uint32_t wbase = sb + wid * (NST * BSTG);
    const char* bbase = (const char*)g_w1b
        + ((size_t)(e * 32) * HDIM + n0 + wn * 64) * 64 + (lr * 64 + sl * 16);

    // A fragments (gathered, row-major xb)
    const char* abase = (const char*)g_xb;
    uint32_t aoff[8];
#pragma unroll
    for (int i = 0; i < 8; i++) {
        int mi = i >> 1, hh = i & 1;
        int tok = g_tok[e * CAP + m0 + wm * 64 + mi * 16 + hh * 8 + gid];
        aoff[i] = (uint32_t)tok * 2048 + (uint32_t)tig * 16;
    }

    float acc[4][8][4];
#pragma unroll
    for (int mi = 0; mi < 4; mi++)
#pragma unroll
        for (int ni = 0; ni < 8; ni++)
#pragma unroll
            for (int q = 0; q < 4; q++) acc[mi][ni][q] = 0.f;

    uint4 a0[8], a1[8];
    MAINLOOP(64u);

    // epilogue: relu(acc + b1) -> g_h1b (tile-major)
    const float* bb = b1 + e * HDIM + n0 + wn * 64 + tig * 2;
    float2 bias[8];
#pragma unroll
    for (int ni = 0; ni < 8; ni++) bias[ni] = *(const float2*)(bb + ni * 8);

#pragma unroll
    for (int mi = 0; mi < 4; mi++)
#pragma unroll
        for (int ph = 0; ph < 2; ph++) {
            int r = m0 + wm * 64 + mi * 16 + ph * 8 + gid;
            if (r < count) {
#pragma unroll
                for (int ch = 0; ch < 2; ch++) {
                    uint4 o;
                    uint32_t* oc = (uint32_t*)&o;
#pragma unroll
                    for (int q = 0; q < 4; q++) {
                        int ni = ch * 4 + q;
                        float v0 = fmaxf(acc[mi][ni][ph * 2 + 0] + bias[ni].x, 0.f);
                        float v1 = fmaxf(acc[mi][ni][ph * 2 + 1] + bias[ni].y, 0.f);
                        oc[q] = pack2(v0, v1);
                    }
                    int c = blockIdx.x * 4 + wn * 2 + ch;   // k-chunk index in h1b
                    *(uint4*)((char*)g_h1b
                        + (((size_t)(e * 32 + c)) * CAP + r) * 64 + tig * 16) = o;
                }
            }
        }
}

// ---------------- GEMM2: out[tok] += w * (h1b @ W2b^T + b2) -------------------
__global__ __launch_bounds__(128, 2) void gemm2_tc(
    const float* __restrict__ b2, float* __restrict__ out)
{
    extern __shared__ char smem[];
    int e = blockIdx.z;
    int count = min(g_cnt[e], CAP);
    int m0 = blockIdx.y * TM;
    if (m0 >= count) return;
    int n0 = blockIdx.x * TN;

    uint32_t sb = smem_u32(smem);
    int tid = threadIdx.x, wid = tid >> 5, lane = tid & 31;
    int wm = wid >> 1, wn = wid & 1, gid = lane >> 2, tig = lane & 3;

    int sl = lane & 3, lr = lane >> 2;
    int sig = (lr >> 1) & 3;
    uint32_t dstoff = (uint32_t)(lr * 64 + ((sl ^ sig) * 16));
    uint32_t wbase = sb + wid * (NST * BSTG);
    const char* bbase = (const char*)g_w2b
        + ((size_t)(e * 32) * HDIM + n0 + wn * 64) * 64 + (lr * 64 + sl * 16);

    // A fragments from tile-major h1b: contiguous rows -> 4 full lines per LDG
    const char* abase = (const char*)g_h1b
        + ((size_t)(e * 32)) * CAP * 64 + tig * 16;
    uint32_t aoff[8];
#pragma unroll
    for (int i = 0; i < 8; i++) {
        int mi = i >> 1, hh = i & 1;
        aoff[i] = (uint32_t)(m0 + wm * 64 + mi * 16 + hh * 8 + gid) * 64;
    }

    float acc[4][8][4];
#pragma unroll
    for (int mi = 0; mi < 4; mi++)
#pragma unroll
        for (int ni = 0; ni < 8; ni++)
#pragma unroll
            for (int q = 0; q < 4; q++) acc[mi][ni][q] = 0.f;

    uint4 a0[8], a1[8];
    MAINLOOP(262144u);   // CAP * 64 bytes per k-chunk

    // epilogue: out[tok] += w * (acc + b2)
    const float* bb = b2 + e * HDIM + n0 + wn * 64 + tig * 2;
    float2 bias[8];
#pragma unroll
    for (int ni = 0; ni < 8; ni++) bias[ni] = *(const float2*)(bb + ni * 8);

#pragma unroll
    for (int mi = 0; mi < 4; mi++)
#pragma unroll
        for (int ph = 0; ph < 2; ph++) {
            int r = m0 + wm * 64 + mi * 16 + ph * 8 + gid;
            if (r < count) {
                int tok = g_tok[e * CAP + r];
                float wv = g_wgt[e * CAP + r];
                float* dp = out + (size_t)tok * HDIM + n0 + wn * 64 + tig * 2;
#pragma unroll
                for (int ni = 0; ni < 8; ni++) {
                    atomicAdd(dp + ni * 8 + 0, (acc[mi][ni][ph * 2 + 0] + bias[ni].x) * wv);
                    atomicAdd(dp + ni * 8 + 1, (acc[mi][ni][ph * 2 + 1] + bias[ni].y) * wv);
                }
            }
        }
}

// ---------------- launch ------------------------------------------------------
extern "C" void kernel_launch(void* const* d_in, const int* in_sizes, int n_in,
                              void* d_out, int out_size)
{
    const float* x  = (const float*)d_in[0];
    const float* rw = (const float*)d_in[1];
    const float* W1 = (const float*)d_in[2];
    const float* b1 = (const float*)d_in[3];
    const float* W2 = (const float*)d_in[4];
    const float* b2 = (const float*)d_in[5];
    float* out = (float*)d_out;

    void* cnt_addr = nullptr;
    cudaGetSymbolAddress(&cnt_addr, g_cnt);
    cudaMemsetAsync(cnt_addr, 0, NEXP * sizeof(int), 0);

    int write_probs = (out_size >= T_TOK * HDIM + T_TOK * NEXP) ? 1 : 0;
    setup_kernel<<<dim3(1024, 4), 256>>>(x, rw, W1, out, write_probs);

    cudaFuncSetAttribute(gemm1_tc, cudaFuncAttributeMaxDynamicSharedMemorySize, SMEM_BYTES);
    cudaFuncSetAttribute(gemm2_tc, cudaFuncAttributeMaxDynamicSharedMemorySize, SMEM_BYTES);

    dim3 grid1(16, CAP / TM, NEXP);     // x<8: compute, x>=8: W2 convert
    dim3 grid2(HDIM / TN, CAP / TM, NEXP);
    gemm1_tc<<<grid1, 128, SMEM_BYTES>>>(b1, W2);
    gemm2_tc<<<grid2, 128, SMEM_BYTES>>>(b2, out);
}

// round 17
// speedup vs baseline: 1.0355x; 1.0355x over previous
#include <cuda_runtime.h>
#include <cuda_bf16.h>
#include <cstdint>
#include <math.h>

// Problem constants
#define T_TOK 8192
#define HDIM  1024
#define NEXP  8
#define CAP   4096

// GEMM tiling: CTA 128x128, 4 warps of 64x64.
// B: warp-private 3-stage cp.async SMEM pipeline, tile-major gmem source.
// A: direct LDG.128 fragments with 1-chunk register prefetch.
#define TM 128
#define TN 128
#define NCH 32
#define BSTG 4096
#define NST 3
#define SMEM_BYTES (4 * NST * BSTG)   // 48KB per CTA

// ---------------- scratch (device globals, zero-init at load) ---------------
// xb:  token-row-major (gather needs it):   [tok][c][slot]   row = 2048B
// w*b: tile-major: [e][c][n][slot]          offset=((e*32+c)*1024+n)*64
// h1b: tile-major: [e][c][r][slot]          offset=((e*32+c)*CAP +r)*64
__device__ int   g_cnt[NEXP];
__device__ int   g_tok[NEXP * CAP];
__device__ float g_wgt[NEXP * CAP];
__device__ uint4 g_xb [(size_t)T_TOK * 128];        // 16MB
__device__ uint4 g_w1b[(size_t)NEXP * HDIM * 128];  // 16MB
__device__ uint4 g_w2b[(size_t)NEXP * HDIM * 128];  // 16MB
__device__ uint4 g_h1b[(size_t)NEXP * CAP * 128];   // 64MB

// ---------------- helpers ----------------------------------------------------
__device__ __forceinline__ uint32_t smem_u32(const void* p) {
    uint32_t a;
    asm("{ .reg .u64 t; cvta.to.shared.u64 t, %1; cvt.u32.u64 %0, t; }" : "=r"(a) : "l"(p));
    return a;
}
__device__ __forceinline__ uint32_t pack2(float lo, float hi) {
    uint32_t r;
    asm("cvt.rn.bf16x2.f32 %0, %1, %2;" : "=r"(r) : "f"(hi), "f"(lo));
    return r;
}
__device__ __forceinline__ uint4 lds128(uint32_t addr) {
    uint4 v;
    asm volatile("ld.shared.v4.b32 {%0,%1,%2,%3}, [%4];"
                 : "=r"(v.x), "=r"(v.y), "=r"(v.z), "=r"(v.w) : "r"(addr));
    return v;
}
__device__ __forceinline__ void cp16ca(uint32_t dst, const void* src) {
    asm volatile("cp.async.ca.shared.global [%0], [%1], 16;" :: "r"(dst), "l"(src));
}
#define CP_COMMIT() asm volatile("cp.async.commit_group;" ::: "memory")
#define CP_WAIT1()  asm volatile("cp.async.wait_group 1;" ::: "memory")

__device__ __forceinline__ void mma16(float* c,
    uint32_t a0, uint32_t a1, uint32_t a2, uint32_t a3, uint32_t b0, uint32_t b1)
{
    asm volatile(
        "mma.sync.aligned.m16n8k16.row.col.f32.bf16.bf16.f32 "
        "{%0,%1,%2,%3}, {%4,%5,%6,%7}, {%8,%9}, {%0,%1,%2,%3};"
        : "+f"(c[0]), "+f"(c[1]), "+f"(c[2]), "+f"(c[3])
        : "r"(a0), "r"(a1), "r"(a2), "r"(a3), "r"(b0), "r"(b1));
}

// permute one 32-float chunk of `src` row into the bf16 slot layout
__device__ __forceinline__ void permute_chunk(
    const float* __restrict__ src, int row, int c, uint4* drow)
{
    const float4* s4 = (const float4*)(src + (size_t)row * HDIM + c * 32);
    float f[32];
#pragma unroll
    for (int i = 0; i < 8; i++) {
        float4 v = s4[i];
        f[4*i] = v.x; f[4*i+1] = v.y; f[4*i+2] = v.z; f[4*i+3] = v.w;
    }
    uint32_t p[16];
#pragma unroll
    for (int P = 0; P < 16; P++) p[P] = pack2(f[2*P], f[2*P+1]);
#pragma unroll
    for (int s = 0; s < 4; s++)
        drow[s] = make_uint4(p[s], p[s+4], p[s+8], p[s+12]);
}

// ---------------- fused setup: router / xb / w1b / w2b / residual copy -------
__global__ __launch_bounds__(256) void setup_kernel(
    const float* __restrict__ x, const float* __restrict__ rw,
    const float* __restrict__ w1, const float* __restrict__ w2,
    float* __restrict__ out, int write_probs)
{
    if (blockIdx.y == 0) {
        // ---- router ----
        int t = blockIdx.x * 8 + (threadIdx.x >> 5);
        int lane = threadIdx.x & 31;

        float acc[NEXP];
#pragma unroll
        for (int e = 0; e < NEXP; e++) acc[e] = 0.f;
        const float* xp = x + (size_t)t * HDIM;
        for (int i = lane; i < HDIM; i += 32) {
            float xv = xp[i];
#pragma unroll
            for (int e = 0; e < NEXP; e++)
                acc[e] = fmaf(xv, rw[e * HDIM + i], acc[e]);
        }
#pragma unroll
        for (int e = 0; e < NEXP; e++)
#pragma unroll
            for (int off = 16; off; off >>= 1)
                acc[e] += __shfl_xor_sync(0xffffffffu, acc[e], off);

        if (lane == 0) {
            float m = acc[0];
#pragma unroll
            for (int e = 1; e < NEXP; e++) m = fmaxf(m, acc[e]);
            float p[NEXP]; float s = 0.f;
#pragma unroll
            for (int e = 0; e < NEXP; e++) { p[e] = expf(acc[e] - m); s += p[e]; }
            float inv_s = 1.f / s;
#pragma unroll
            for (int e = 0; e < NEXP; e++) p[e] *= inv_s;

            if (write_probs) {
                float* pr = out + (size_t)T_TOK * HDIM + (size_t)t * NEXP;
#pragma unroll
                for (int e = 0; e < NEXP; e++) pr[e] = p[e];
            }
            int i0 = 0;
#pragma unroll
            for (int e = 1; e < NEXP; e++) if (p[e] > p[i0]) i0 = e;
            int i1 = (i0 == 0) ? 1 : 0;
#pragma unroll
            for (int e = 0; e < NEXP; e++) if (e != i0 && p[e] > p[i1]) i1 = e;

            float v0 = p[i0], v1 = p[i1];
            float invw = 1.f / (v0 + v1);
            int pos0 = atomicAdd(&g_cnt[i0], 1);
            if (pos0 < CAP) { g_tok[i0 * CAP + pos0] = t; g_wgt[i0 * CAP + pos0] = v0 * invw; }
            int pos1 = atomicAdd(&g_cnt[i1], 1);
            if (pos1 < CAP) { g_tok[i1 * CAP + pos1] = t; g_wgt[i1 * CAP + pos1] = v1 * invw; }
        }
    } else if (blockIdx.y == 1) {
        // ---- xb: token-row-major permute ----
        int idx = blockIdx.x * 256 + threadIdx.x;
        int row = idx >> 5, c = idx & 31;
        permute_chunk(x, row, c, g_xb + ((size_t)row * 32 + c) * 4);
    } else if (blockIdx.y == 2) {
        // ---- w1b: tile-major permute ----
        int idx = blockIdx.x * 256 + threadIdx.x;
        int row = idx >> 5, c = idx & 31;
        int e = row >> 10, n = row & 1023;
        permute_chunk(w1, row, c, g_w1b + (((size_t)(e * 32 + c)) * HDIM + n) * 4);
    } else if (blockIdx.y == 3) {
        // ---- w2b: tile-major permute ----
        int idx = blockIdx.x * 256 + threadIdx.x;
        int row = idx >> 5, c = idx & 31;
        int e = row >> 10, n = row & 1023;
        permute_chunk(w2, row, c, g_w2b + (((size_t)(e * 32 + c)) * HDIM + n) * 4);
    } else {
        // ---- residual copy: out[0:T*H] = x ----
        const float4* s = (const float4*)x;
        float4* d = (float4*)out;
        int t0 = blockIdx.x * 256 + threadIdx.x;
#pragma unroll
        for (int i = 0; i < 8; i++)
            d[t0 + i * 262144] = s[t0 + i * 262144];
    }
}

// ---------------- compute: B fragments from warp-private SMEM, A from regs ---
__device__ __forceinline__ void compute_chunkB(
    uint32_t breg, const uint4 a[8], float acc[4][8][4], int gid, int tig)
{
    uint32_t toff = (uint32_t)((tig ^ ((gid >> 1) & 3)) * 16);
#pragma unroll
    for (int ni = 0; ni < 8; ni++) {
        uint4 fb = lds128(breg + (ni * 8 + gid) * 64 + toff);
#pragma unroll
        for (int mi = 0; mi < 4; mi++) {
            float* c = acc[mi][ni];
            mma16(c, a[mi*2].x, a[mi*2+1].x, a[mi*2].y, a[mi*2+1].y, fb.x, fb.y);
            mma16(c, a[mi*2].z, a[mi*2+1].z, a[mi*2].w, a[mi*2+1].w, fb.z, fb.w);
        }
    }
}

// stage B chunk cc (tile-major source: 512B contiguous per cp.async instr)
#define STAGE_B(cc, st) do { \
    uint32_t _d = wbase + (uint32_t)(st) * BSTG + dstoff; \
    uint32_t _g = (uint32_t)(cc) * 65536; \
    _Pragma("unroll") \
    for (int i = 0; i < 8; i++) \
        cp16ca(_d + i * 512, bbase + _g + i * 512); \
} while (0)

#define LOAD_A(dst, cc, astride) do { \
    _Pragma("unroll") \
    for (int i = 0; i < 8; i++) \
        (dst)[i] = __ldg((const uint4*)(abase + aoff[i] + (uint32_t)(cc) * (astride))); \
} while (0)

#define MAINLOOP(astride) do { \
    LOAD_A(a0, 0, astride); \
    STAGE_B(0, 0); CP_COMMIT(); \
    STAGE_B(1, 1); CP_COMMIT(); \
    int fill = 2, cur = 0; \
    for (int c = 0; c < NCH; c += 2) { \
        CP_WAIT1(); __syncwarp(); \
        if (c + 2 < NCH) STAGE_B(c + 2, fill); \
        CP_COMMIT(); \
        fill = (fill == 2) ? 0 : fill + 1; \
        LOAD_A(a1, c + 1, astride); \
        compute_chunkB(wbase + cur * BSTG, a0, acc, gid, tig); \
        cur = (cur == 2) ? 0 : cur + 1; \
        CP_WAIT1(); __syncwarp(); \
        if (c + 3 < NCH) STAGE_B(c + 3, fill); \
        CP_COMMIT(); \
        fill = (fill == 2) ? 0 : fill + 1; \
        if (c + 2 < NCH) LOAD_A(a0, c + 2, astride); \
        compute_chunkB(wbase + cur * BSTG, a1, acc, gid, tig); \
        cur = (cur == 2) ? 0 : cur + 1; \
    } \
} while (0)

// ---------------- GEMM1: h1b = relu(xb[gather] @ W1b^T + b1) -----------------
__global__ __launch_bounds__(128, 2) void gemm1_tc(const float* __restrict__ b1)
{
    extern __shared__ char smem[];
    int e = blockIdx.z;
    int count = min(g_cnt[e], CAP);
    int m0 = blockIdx.y * TM;
    if (m0 >= count) return;
    int n0 = blockIdx.x * TN;

    uint32_t sb = smem_u32(smem);
    int tid = threadIdx.x, wid = tid >> 5, lane = tid & 31;
    int wm = wid >> 1, wn = wid & 1, gid = lane >> 2, tig = lane & 3;

    // B staging: tile-major w1b; per-lane contiguous source offset
    int sl = lane & 3, lr = lane >> 2;
    int sig = (lr >> 1) & 3;
    uint32_t dstoff = (uint32_t)(lr * 64 + ((sl ^ sig) * 16));
    uint32_t wbase = sb + wid * (NST * BSTG);
    const char* bbase = (const char*)g_w1b
        + ((size_t)(e * 32) * HDIM + n0 + wn * 64) * 64 + (lr * 64 + sl * 16);

    // A fragments (gathered, row-major xb)
    const char* abase = (const char*)g_xb;
    uint32_t aoff[8];
#pragma unroll
    for (int i = 0; i < 8; i++) {
        int mi = i >> 1, hh = i & 1;
        int tok = g_tok[e * CAP + m0 + wm * 64 + mi * 16 + hh * 8 + gid];
        aoff[i] = (uint32_t)tok * 2048 + (uint32_t)tig * 16;
    }

    float acc[4][8][4];
#pragma unroll
    for (int mi = 0; mi < 4; mi++)
#pragma unroll
        for (int ni = 0; ni < 8; ni++)
#pragma unroll
            for (int q = 0; q < 4; q++) acc[mi][ni][q] = 0.f;

    uint4 a0[8], a1[8];
    MAINLOOP(64u);

    // epilogue: relu(acc + b1) -> g_h1b (tile-major)
    const float* bb = b1 + e * HDIM + n0 + wn * 64 + tig * 2;
    float2 bias[8];
#pragma unroll
    for (int ni = 0; ni < 8; ni++) bias[ni] = *(const float2*)(bb + ni * 8);

#pragma unroll
    for (int mi = 0; mi < 4; mi++)
#pragma unroll
        for (int ph = 0; ph < 2; ph++) {
            int r = m0 + wm * 64 + mi * 16 + ph * 8 + gid;
            if (r < count) {
#pragma unroll
                for (int ch = 0; ch < 2; ch++) {
                    uint4 o;
                    uint32_t* oc = (uint32_t*)&o;
#pragma unroll
                    for (int q = 0; q < 4; q++) {
                        int ni = ch * 4 + q;
                        float v0 = fmaxf(acc[mi][ni][ph * 2 + 0] + bias[ni].x, 0.f);
                        float v1 = fmaxf(acc[mi][ni][ph * 2 + 1] + bias[ni].y, 0.f);
                        oc[q] = pack2(v0, v1);
                    }
                    int c = blockIdx.x * 4 + wn * 2 + ch;   // k-chunk index in h1b
                    *(uint4*)((char*)g_h1b
                        + (((size_t)(e * 32 + c)) * CAP + r) * 64 + tig * 16) = o;
                }
            }
        }
}

// ---------------- GEMM2: out[tok] += w * (h1b @ W2b^T + b2) -------------------
__global__ __launch_bounds__(128, 2) void gemm2_tc(
    const float* __restrict__ b2, float* __restrict__ out)
{
    extern __shared__ char smem[];
    int e = blockIdx.z;
    int count = min(g_cnt[e], CAP);
    int m0 = blockIdx.y * TM;
    if (m0 >= count) return;
    int n0 = blockIdx.x * TN;

    uint32_t sb = smem_u32(smem);
    int tid = threadIdx.x, wid = tid >> 5, lane = tid & 31;
    int wm = wid >> 1, wn = wid & 1, gid = lane >> 2, tig = lane & 3;

    int sl = lane & 3, lr = lane >> 2;
    int sig = (lr >> 1) & 3;
    uint32_t dstoff = (uint32_t)(lr * 64 + ((sl ^ sig) * 16));
    uint32_t wbase = sb + wid * (NST * BSTG);
    const char* bbase = (const char*)g_w2b
        + ((size_t)(e * 32) * HDIM + n0 + wn * 64) * 64 + (lr * 64 + sl * 16);

    // A fragments from tile-major h1b: contiguous rows -> 4 full lines per LDG
    const char* abase = (const char*)g_h1b
        + ((size_t)(e * 32)) * CAP * 64 + tig * 16;
    uint32_t aoff[8];
#pragma unroll
    for (int i = 0; i < 8; i++) {
        int mi = i >> 1, hh = i & 1;
        aoff[i] = (uint32_t)(m0 + wm * 64 + mi * 16 + hh * 8 + gid) * 64;
    }

    float acc[4][8][4];
#pragma unroll
    for (int mi = 0; mi < 4; mi++)
#pragma unroll
        for (int ni = 0; ni < 8; ni++)
#pragma unroll
            for (int q = 0; q < 4; q++) acc[mi][ni][q] = 0.f;

    uint4 a0[8], a1[8];
    MAINLOOP(262144u);   // CAP * 64 bytes per k-chunk

    // epilogue: out[tok] += w * (acc + b2)
    const float* bb = b2 + e * HDIM + n0 + wn * 64 + tig * 2;
    float2 bias[8];
#pragma unroll
    for (int ni = 0; ni < 8; ni++) bias[ni] = *(const float2*)(bb + ni * 8);

#pragma unroll
    for (int mi = 0; mi < 4; mi++)
#pragma unroll
        for (int ph = 0; ph < 2; ph++) {
            int r = m0 + wm * 64 + mi * 16 + ph * 8 + gid;
            if (r < count) {
                int tok = g_tok[e * CAP + r];
                float wv = g_wgt[e * CAP + r];
                float* dp = out + (size_t)tok * HDIM + n0 + wn * 64 + tig * 2;
#pragma unroll
                for (int ni = 0; ni < 8; ni++) {
                    atomicAdd(dp + ni * 8 + 0, (acc[mi][ni][ph * 2 + 0] + bias[ni].x) * wv);
                    atomicAdd(dp + ni * 8 + 1, (acc[mi][ni][ph * 2 + 1] + bias[ni].y) * wv);
                }
            }
        }
}

// ---------------- launch ------------------------------------------------------
extern "C" void kernel_launch(void* const* d_in, const int* in_sizes, int n_in,
                              void* d_out, int out_size)
{
    const float* x  = (const float*)d_in[0];
    const float* rw = (const float*)d_in[1];
    const float* W1 = (const float*)d_in[2];
    const float* b1 = (const float*)d_in[3];
    const float* W2 = (const float*)d_in[4];
    const float* b2 = (const float*)d_in[5];
    float* out = (float*)d_out;

    void* cnt_addr = nullptr;
    cudaGetSymbolAddress(&cnt_addr, g_cnt);
    cudaMemsetAsync(cnt_addr, 0, NEXP * sizeof(int), 0);

    int write_probs = (out_size >= T_TOK * HDIM + T_TOK * NEXP) ? 1 : 0;
    setup_kernel<<<dim3(1024, 5), 256>>>(x, rw, W1, W2, out, write_probs);

    cudaFuncSetAttribute(gemm1_tc, cudaFuncAttributeMaxDynamicSharedMemorySize, SMEM_BYTES);
    cudaFuncSetAttribute(gemm2_tc, cudaFuncAttributeMaxDynamicSharedMemorySize, SMEM_BYTES);

    dim3 grid(HDIM / TN, CAP / TM, NEXP);
    gemm1_tc<<<grid, 128, SMEM_BYTES>>>(b1);
    gemm2_tc<<<grid, 128, SMEM_BYTES>>>(b2, out);
}